// round 2
// baseline (speedup 1.0000x reference)
#include <cuda_runtime.h>
#include <cstdint>
#include <cstddef>

#define BB 16
#define AA 65536
#define TT 32
#define CC 21
#define NB1 2048
#define NB2 4096
#define CAP 262144
#define THR 256
#define SST 32

struct State {
    unsigned long long packed[BB][TT];   // force-match argmax keys
    unsigned int forced[BB][AA / 32];    // forced-positive bitmask
    int numpos[BB], nneg[BB], kval[BB], blo[BB], redo[BB], cnt[BB];
    float possum[BB], bboxsum[BB], confl[BB], bboxl[BB];
    unsigned int h0[BB][NB1];            // sampled coarse histogram
    unsigned int fcnt[BB][NB1];          // fallback histogram
    float fsum[BB][NB1];
};
__device__ State g;
__device__ float g_buf[BB][CAP];         // compacted candidate focal values
__device__ float g_maxiou[BB * AA];
__device__ unsigned char g_bestt[BB * AA];

// ---------------------------------------------------------------- helpers
__device__ __forceinline__ void softmax21(float* x) {
    float m = x[0];
#pragma unroll
    for (int c = 1; c < CC; c++) m = fmaxf(m, x[c]);
    float s = 0.f;
#pragma unroll
    for (int c = 0; c < CC; c++) { x[c] = __expf(x[c] - m); s += x[c]; }
    float inv = 1.0f / s;
#pragma unroll
    for (int c = 0; c < CC; c++) x[c] *= inv;
}

__device__ __forceinline__ float focal_fn(float p, bool ispos) {
    float pt = ispos ? p : 1.0f - p;
    float af = ispos ? 0.25f : 0.75f;
    float om = 1.0f - pt;
    return -af * om * om * __logf(fmaxf(pt, 1e-6f));
}

// -------------------------------------------------------------- k0: zero
__global__ void kZero() {
    size_t n = sizeof(State) / 4;
    size_t i = (size_t)blockIdx.x * blockDim.x + threadIdx.x;
    if (i < n) ((unsigned int*)&g)[i] = 0u;
}

// ------------------------------------------- k1: IoU, argmaxes, counts
__global__ void kIoU(const float* __restrict__ anchors, const float* __restrict__ tb) {
    int b = blockIdx.y;
    int tid = threadIdx.x;
    int a = blockIdx.x * THR + tid;
    __shared__ float stb[TT * 4];
    __shared__ unsigned long long smax[TT];
    __shared__ int snp, snn;
    if (tid < TT * 4) stb[tid] = tb[b * TT * 4 + tid];
    if (tid < TT) smax[tid] = 0ull;
    if (tid == 0) { snp = 0; snn = 0; }
    __syncthreads();

    float4 av = ((const float4*)anchors)[a];
    float aarea = (av.z - av.x) * (av.w - av.y);
    float best = -1.f;
    int bt = 0;
    unsigned long long low = (unsigned long long)(0xFFFFFFFFu - (unsigned)a);
#pragma unroll 8
    for (int t = 0; t < TT; t++) {
        float bx1 = stb[4 * t], by1 = stb[4 * t + 1];
        float bx2 = stb[4 * t + 2], by2 = stb[4 * t + 3];
        float x1 = fmaxf(av.x, bx1), y1 = fmaxf(av.y, by1);
        float x2 = fminf(av.z, bx2), y2 = fminf(av.w, by2);
        float inter = fmaxf(x2 - x1, 0.f) * fmaxf(y2 - y1, 0.f);
        float ba = (bx2 - bx1) * (by2 - by1);
        float iou = inter / (aarea + ba - inter + 1e-6f);
        if (iou > best) { best = iou; bt = t; }   // strict >: first-index argmax
        unsigned long long cand = ((unsigned long long)__float_as_uint(iou) << 32) | low;
        if (cand > smax[t]) atomicMax(&smax[t], cand);
    }
    g_maxiou[b * AA + a] = best;
    g_bestt[b * AA + a] = (unsigned char)bt;

    unsigned pb = __ballot_sync(0xFFFFFFFFu, best >= 0.5f);
    unsigned nb = __ballot_sync(0xFFFFFFFFu, best < 0.4f);
    if ((tid & 31) == 0) { atomicAdd(&snp, __popc(pb)); atomicAdd(&snn, __popc(nb)); }
    __syncthreads();
    if (tid < TT) { unsigned long long v = smax[tid]; if (v) atomicMax(&g.packed[b][tid], v); }
    if (tid == 0) { atomicAdd(&g.numpos[b], snp); atomicAdd(&g.nneg[b], snn); }
}

// ------------------------------------- k2: apply force-match, fix counts
__global__ void kForce() {
    int i = blockIdx.x * blockDim.x + threadIdx.x;
    if (i >= BB * TT) return;
    int b = i / TT, t = i % TT;
    unsigned a = 0xFFFFFFFFu - (unsigned)(g.packed[b][t] & 0xFFFFFFFFull);
    unsigned bit = 1u << (a & 31);
    unsigned old = atomicOr(&g.forced[b][a >> 5], bit);
    if (!(old & bit)) {
        float mi = g_maxiou[b * AA + a];
        if (mi < 0.5f) atomicAdd(&g.numpos[b], 1);
        if (mi < 0.4f) atomicAdd(&g.nneg[b], -1);
    }
}

// ------------------------------- k3: 1/32-sampled coarse focal histogram
__global__ void kSample(const float* __restrict__ conf) {
    int b = blockIdx.y;
    int tid = threadIdx.x;
    int a = (blockIdx.x * THR + tid) * SST;
    __shared__ unsigned int sh[NB1];
    for (int i = tid; i < NB1; i += THR) sh[i] = 0;
    __syncthreads();
    float mi = g_maxiou[b * AA + a];
    bool forced = (g.forced[b][a >> 5] >> (a & 31)) & 1;
    if (mi < 0.4f && !forced) {
        const float* cp = conf + ((size_t)b * AA + a) * CC;
        float p[CC];
#pragma unroll
        for (int c = 0; c < CC; c++) p[c] = cp[c];
        softmax21(p);
#pragma unroll
        for (int c = 0; c < CC; c++) {
            float f = focal_fn(p[c], false);
            atomicAdd(&sh[__float_as_uint(f) >> 20], 1u);
        }
    }
    __syncthreads();
    for (int i = tid; i < NB1; i += THR)
        if (sh[i]) atomicAdd(&g.h0[b][i], sh[i]);
}

// --------------------------------- k4: pick conservative threshold bin, k
__global__ void kThresh() {
    int b = blockIdx.x, tid = threadIdx.x;
    __shared__ unsigned int sh[NB1];
    for (int i = tid; i < NB1; i += THR) sh[i] = g.h0[b][i];
    __syncthreads();
    if (tid) return;
    long long np = g.numpos[b], nn = g.nneg[b];
    long long k = 3 * np; if (nn < k) k = nn;
    g.kval[b] = (int)k;
    if (k <= 0) { g.blo[b] = NB1; return; }
    long long target = k / 16 + 64;   // estimated survivors ~ 2k + 2048
    long long cum = 0;
    int bin = NB1 - 1;
    for (; bin >= 0; bin--) { cum += sh[bin]; if (cum >= target) break; }
    g.blo[b] = bin < 0 ? 0 : bin;
}

// ------------------- k5: main pass: focal, pos_sum, bbox loss, compaction
__global__ void kMain(const float* __restrict__ conf, const float* __restrict__ bbox,
                      const float* __restrict__ tb, const int* __restrict__ tl) {
    int b = blockIdx.y;
    int tid = threadIdx.x;
    int a0 = blockIdx.x * THR, a = a0 + tid;
    __shared__ float sc[THR * CC];
    __shared__ float stb[TT * 4];
    __shared__ int stl[TT];
    if (tid < TT * 4) stb[tid] = tb[b * TT * 4 + tid];
    if (tid < TT) stl[tid] = tl[b * TT + tid];
    size_t cb = ((size_t)b * AA + a0) * CC;
    for (int i = tid; i < THR * CC; i += THR) sc[i] = conf[cb + i];
    __syncthreads();

    float mi = g_maxiou[b * AA + a];
    bool forced = (g.forced[b][a >> 5] >> (a & 31)) & 1;
    bool pos = (mi >= 0.5f) || forced;
    bool neg = (mi < 0.4f) && !forced;
    if (!pos && !neg) return;
    int bt = g_bestt[b * AA + a];
    int blo = g.blo[b];

    float p[CC];
#pragma unroll
    for (int c = 0; c < CC; c++) p[c] = sc[tid * CC + c];  // stride 21: conflict-free
    softmax21(p);

    if (pos) {
        int tc = stl[bt];
        float ps = 0.f;
#pragma unroll
        for (int c = 0; c < CC; c++) ps += focal_fn(p[c], c == tc);
        atomicAdd(&g.possum[b], ps);

        float4 bp = ((const float4*)bbox)[(size_t)b * AA + a];
        float t0 = stb[bt * 4], t1 = stb[bt * 4 + 1];
        float t2 = stb[bt * 4 + 2], t3 = stb[bt * 4 + 3];
        float x1 = fmaxf(bp.x, t0), y1 = fmaxf(bp.y, t1);
        float x2 = fminf(bp.z, t2), y2 = fminf(bp.w, t3);
        float inter = fmaxf(x2 - x1, 0.f) * fmaxf(y2 - y1, 0.f);
        float a1 = (bp.z - bp.x) * (bp.w - bp.y);
        float a2 = (t2 - t0) * (t3 - t1);
        float uni = a1 + a2 - inter;
        float iou = inter / (uni + 1e-6f);
        float ex1 = fminf(bp.x, t0), ey1 = fminf(bp.y, t1);
        float ex2 = fmaxf(bp.z, t2), ey2 = fmaxf(bp.w, t3);
        float enc = (ex2 - ex1) * (ey2 - ey1);
        float gl = 1.f - (iou - (enc - uni) / (enc + 1e-6f));
        float l1 = 0.f, d, ad;
        d = bp.x - t0; ad = fabsf(d); l1 += (ad < 1.f) ? 0.5f * d * d : ad - 0.5f;
        d = bp.y - t1; ad = fabsf(d); l1 += (ad < 1.f) ? 0.5f * d * d : ad - 0.5f;
        d = bp.z - t2; ad = fabsf(d); l1 += (ad < 1.f) ? 0.5f * d * d : ad - 0.5f;
        d = bp.w - t3; ad = fabsf(d); l1 += (ad < 1.f) ? 0.5f * d * d : ad - 0.5f;
        l1 *= 0.25f;
        atomicAdd(&g.bboxsum[b], gl + 0.5f * l1);
    } else {  // neg
#pragma unroll
        for (int c = 0; c < CC; c++) {
            float f = focal_fn(p[c], false);
            if ((int)(__float_as_uint(f) >> 20) >= blo) {
                int idx = atomicAdd(&g.cnt[b], 1);
                if (idx < CAP) g_buf[b][idx] = f;
            }
        }
    }
}

// ----------------- k6: exact top-k on compacted values (2-level radix)
__global__ void kSelect() {
    int b = blockIdx.x, tid = threadIdx.x;
    __shared__ unsigned int hc[NB2];
    __shared__ float hs[NB2];
    __shared__ int s_bstar;
    __shared__ long long s_rem;
    __shared__ float s_above;
    int n = g.cnt[b];
    long long k = g.kval[b];
    bool bad = (n > CAP) || ((long long)n < k);
    float topk = 0.f;
    if (k > 0 && !bad) {
        for (int i = tid; i < NB1; i += blockDim.x) { hc[i] = 0; hs[i] = 0.f; }
        __syncthreads();
        for (int i = tid; i < n; i += blockDim.x) {
            float v = g_buf[b][i];
            int bin = __float_as_uint(v) >> 20;
            atomicAdd(&hc[bin], 1u);
            atomicAdd(&hs[bin], v);
        }
        __syncthreads();
        if (tid == 0) {
            long long cum = 0; float ab = 0.f; int bin = NB1 - 1;
            for (; bin > 0; bin--) {
                unsigned c = hc[bin];
                if (cum + (long long)c >= k) break;
                cum += c; ab += hs[bin];
            }
            long long rem = k - cum;
            if (rem >= (long long)hc[bin]) { ab += hs[bin]; rem = 0; }
            s_bstar = bin; s_rem = rem; s_above = ab;
        }
        __syncthreads();
        int bstar = s_bstar;
        long long rem = s_rem;
        if (rem > 0) {
            for (int i = tid; i < NB2; i += blockDim.x) { hc[i] = 0; hs[i] = 0.f; }
            __syncthreads();
            for (int i = tid; i < n; i += blockDim.x) {
                float v = g_buf[b][i];
                unsigned bits = __float_as_uint(v);
                if ((int)(bits >> 20) == bstar) {
                    int sb = (bits >> 8) & 0xFFF;
                    atomicAdd(&hc[sb], 1u);
                    atomicAdd(&hs[sb], v);
                }
            }
            __syncthreads();
            if (tid == 0) {
                long long cum = 0; float ab2 = 0.f; int sb = NB2 - 1;
                for (; sb > 0; sb--) {
                    unsigned c = hc[sb];
                    if (cum + (long long)c >= rem) break;
                    cum += c; ab2 += hs[sb];
                }
                long long r2 = rem - cum;
                float part = (r2 > 0 && hc[sb] > 0) ? (float)r2 * (hs[sb] / (float)hc[sb]) : 0.f;
                s_above = s_above + ab2 + part;
            }
            __syncthreads();
        }
        topk = s_above;
    }
    if (tid == 0) {
        long long np = g.numpos[b];
        if (bad && k > 0) {
            g.redo[b] = 1;
        } else {
            long long dn = np + k; if (dn < 1) dn = 1;
            g.confl[b] = (g.possum[b] + topk) / (float)dn;
        }
        g.bboxl[b] = (np > 0) ? g.bboxsum[b] / (float)np : 0.f;
    }
}

// --------- k7/k8: fallback (full histogram) — uniform early-out when idle
__global__ void kFbHist(const float* __restrict__ conf) {
    int b = blockIdx.y;
    if (g.redo[b] == 0) return;
    int tid = threadIdx.x;
    int a0 = blockIdx.x * THR, a = a0 + tid;
    __shared__ float sc[THR * CC];
    __shared__ unsigned int hc[NB1];
    __shared__ float hs[NB1];
    for (int i = tid; i < NB1; i += THR) { hc[i] = 0; hs[i] = 0.f; }
    size_t cb = ((size_t)b * AA + a0) * CC;
    for (int i = tid; i < THR * CC; i += THR) sc[i] = conf[cb + i];
    __syncthreads();
    float mi = g_maxiou[b * AA + a];
    bool forced = (g.forced[b][a >> 5] >> (a & 31)) & 1;
    if (mi < 0.4f && !forced) {
        float p[CC];
#pragma unroll
        for (int c = 0; c < CC; c++) p[c] = sc[tid * CC + c];
        softmax21(p);
#pragma unroll
        for (int c = 0; c < CC; c++) {
            float f = focal_fn(p[c], false);
            int bin = __float_as_uint(f) >> 20;
            atomicAdd(&hc[bin], 1u);
            atomicAdd(&hs[bin], f);
        }
    }
    __syncthreads();
    for (int i = tid; i < NB1; i += THR)
        if (hc[i]) { atomicAdd(&g.fcnt[b][i], hc[i]); atomicAdd(&g.fsum[b][i], hs[i]); }
}

__global__ void kFbSel() {
    int b = blockIdx.x;
    if (g.redo[b] == 0) return;
    int tid = threadIdx.x;
    __shared__ unsigned int hc[NB1];
    __shared__ float hs[NB1];
    for (int i = tid; i < NB1; i += THR) { hc[i] = g.fcnt[b][i]; hs[i] = g.fsum[b][i]; }
    __syncthreads();
    if (tid) return;
    long long k = g.kval[b], np = g.numpos[b];
    long long cum = 0; float ab = 0.f; int bin = NB1 - 1;
    for (; bin > 0; bin--) {
        unsigned c = hc[bin];
        if (cum + (long long)c >= k) break;
        cum += c; ab += hs[bin];
    }
    long long rem = k - cum;
    if (rem > 0 && hc[bin] > 0) ab += (float)rem * (hs[bin] / (float)hc[bin]);
    long long dn = np + k; if (dn < 1) dn = 1;
    g.confl[b] = (g.possum[b] + ab) / (float)dn;
}

// --------------------------------------------------------- k9: finalize
__global__ void kFinal(float* out) {
    if (threadIdx.x == 0) {
        float cs = 0.f, bs = 0.f;
        for (int b = 0; b < BB; b++) { cs += g.confl[b]; bs += g.bboxl[b]; }
        cs *= (1.0f / BB); bs *= (1.0f / BB);
        out[0] = cs + bs;
        out[1] = cs;
        out[2] = bs;
    }
}

// ---------------------------------------------------------------- launch
extern "C" void kernel_launch(void* const* d_in, const int* in_sizes, int n_in,
                              void* d_out, int out_size) {
    const float* conf = (const float*)d_in[0];
    const float* bbox = (const float*)d_in[1];
    const float* anch = (const float*)d_in[2];
    const float* tb = (const float*)d_in[3];
    const int* tl = (const int*)d_in[4];
    float* out = (float*)d_out;

    int nz = (int)(sizeof(State) / 4);
    kZero<<<(nz + 255) / 256, 256>>>();
    kIoU<<<dim3(AA / THR, BB), THR>>>(anch, tb);
    kForce<<<1, BB * TT>>>();
    kSample<<<dim3(AA / SST / THR, BB), THR>>>(conf);
    kThresh<<<BB, THR>>>();
    kMain<<<dim3(AA / THR, BB), THR>>>(conf, bbox, tb, tl);
    kSelect<<<BB, 512>>>();
    kFbHist<<<dim3(AA / THR, BB), THR>>>(conf);
    kFbSel<<<BB, THR>>>();
    kFinal<<<1, 32>>>(out);
}

// round 4
// speedup vs baseline: 1.4466x; 1.4466x over previous
#include <cuda_runtime.h>
#include <cstdint>
#include <cstddef>

#define BB 16
#define AA 65536
#define TT 32
#define CC 21
#define NB1 2048
#define NB2 4096
#define CAP 262144
#define THR 256

struct State {
    unsigned long long packed[BB][TT];   // force-match argmax keys
    unsigned int forced[BB][AA / 32];    // forced-positive bitmask
    int numpos[BB], nneg[BB], kval[BB], blo[BB], redo[BB], cnt[BB];
    float possum[BB], bboxsum[BB], confl[BB], bboxl[BB];
    unsigned int h0[BB][NB1];            // sampled coarse histogram
    unsigned int fcnt[BB][NB1];          // fallback histogram
    float fsum[BB][NB1];
};
__device__ State g;
__device__ float g_buf[BB][CAP];         // compacted candidate focal values
__device__ float g_maxiou[BB * AA];
__device__ unsigned char g_bestt[BB * AA];

// ---------------------------------------------------------------- helpers
__device__ __forceinline__ void softmax21(float* x) {
    float m = x[0];
#pragma unroll
    for (int c = 1; c < CC; c++) m = fmaxf(m, x[c]);
    float s = 0.f;
#pragma unroll
    for (int c = 0; c < CC; c++) { x[c] = __expf(x[c] - m); s += x[c]; }
    float inv = 1.0f / s;
#pragma unroll
    for (int c = 0; c < CC; c++) x[c] *= inv;
}

__device__ __forceinline__ float focal_fn(float p, bool ispos) {
    float pt = ispos ? p : 1.0f - p;
    float af = ispos ? 0.25f : 0.75f;
    float om = 1.0f - pt;
    return -af * om * om * __logf(fmaxf(pt, 1e-6f));
}

// bin index of a focal value; sign bit masked so -0.0 -> bin 0 (never OOB)
__device__ __forceinline__ int focal_bin(float f) {
    return (int)((__float_as_uint(f) & 0x7FFFFFFFu) >> 20);
}

// Block-wide (exactly 256 threads) descending bin selection over NB bins.
// Finds bin* where cumulative count from the top first reaches k.
// o_found, o_bin, o_cum (count strictly above bin*), o_sum (value-sum above).
template <int NB, bool WS>
__device__ __forceinline__ void suffix_select(
    const unsigned* hc, const float* hs, long long k,
    unsigned* s_scnt, float* s_ssum,
    int* o_found, int* o_bin, long long* o_cum, float* o_sum)
{
    const int tid = threadIdx.x;          // requires blockDim.x == 256
    const int CH = NB / 256;
    unsigned myc = 0; float myf = 0.f;
#pragma unroll
    for (int j = 0; j < CH; j++) {
        myc += hc[tid * CH + j];
        if (WS) myf += hs[tid * CH + j];
    }
    s_scnt[tid] = myc;
    if (WS) s_ssum[tid] = myf;
    __syncthreads();
    for (int off = 1; off < 256; off <<= 1) {   // inclusive suffix scan
        unsigned vc = (tid + off < 256) ? s_scnt[tid + off] : 0u;
        float vf = 0.f;
        if (WS) vf = (tid + off < 256) ? s_ssum[tid + off] : 0.f;
        __syncthreads();
        s_scnt[tid] += vc;
        if (WS) s_ssum[tid] += vf;
        __syncthreads();
    }
    if (tid == 0) {
        *o_found = ((long long)s_scnt[0] >= k) ? 1 : 0;
        *o_bin = 0; *o_cum = 0; *o_sum = 0.f;
    }
    __syncthreads();
    if (*o_found) {
        long long S = (long long)s_scnt[tid];
        long long A = S - (long long)myc;
        if (A < k && S >= k) {                    // unique crossing chunk
            long long cum = A;
            float ab = WS ? (s_ssum[tid] - myf) : 0.f;
            int bin = tid * CH;
            for (int j = CH - 1; j >= 0; j--) {
                int bb = tid * CH + j;
                unsigned c = hc[bb];
                if (cum + (long long)c >= k) { bin = bb; break; }
                cum += c;
                if (WS) ab += hs[bb];
            }
            *o_bin = bin; *o_cum = cum; *o_sum = ab;
        }
    }
    __syncthreads();
}

// -------------------------------------------------------------- k0: zero
__global__ void kZero() {
    size_t n = sizeof(State) / 4;
    size_t i = (size_t)blockIdx.x * blockDim.x + threadIdx.x;
    if (i < n) ((unsigned int*)&g)[i] = 0u;
}

// --------------- k1: IoU, argmaxes, counts + fused sampled histogram
__global__ void kIoUSamp(const float* __restrict__ anchors, const float* __restrict__ tb,
                         const float* __restrict__ conf) {
    int b = blockIdx.y;
    int tid = threadIdx.x;
    int a = blockIdx.x * THR + tid;
    __shared__ float stb[TT * 4];
    __shared__ float sarea[TT];
    __shared__ unsigned long long smax[TT];
    __shared__ int snp, snn;
    __shared__ unsigned int sh[NB1];
    for (int i = tid; i < NB1; i += THR) sh[i] = 0;
    if (tid < TT * 4) stb[tid] = tb[b * TT * 4 + tid];
    if (tid < TT) smax[tid] = 0ull;
    if (tid == 0) { snp = 0; snn = 0; }
    __syncthreads();
    if (tid < TT) sarea[tid] = (stb[4 * tid + 2] - stb[4 * tid]) * (stb[4 * tid + 3] - stb[4 * tid + 1]);
    __syncthreads();

    float4 av = ((const float4*)anchors)[a];
    float aarea = (av.z - av.x) * (av.w - av.y);
    float best = -1.f;
    int bt = 0;
    unsigned long long low = (unsigned long long)(0xFFFFFFFFu - (unsigned)a);
#pragma unroll 8
    for (int t = 0; t < TT; t++) {
        float bx1 = stb[4 * t], by1 = stb[4 * t + 1];
        float bx2 = stb[4 * t + 2], by2 = stb[4 * t + 3];
        float x1 = fmaxf(av.x, bx1), y1 = fmaxf(av.y, by1);
        float x2 = fminf(av.z, bx2), y2 = fminf(av.w, by2);
        float inter = fmaxf(x2 - x1, 0.f) * fmaxf(y2 - y1, 0.f);
        float iou = inter / (aarea + sarea[t] - inter + 1e-6f);
        if (iou > best) { best = iou; bt = t; }   // strict >: first-index argmax
        unsigned long long cand = ((unsigned long long)__float_as_uint(iou) << 32) | low;
        if (cand > smax[t]) atomicMax(&smax[t], cand);
    }
    g_maxiou[b * AA + a] = best;
    g_bestt[b * AA + a] = (unsigned char)bt;

    unsigned pb = __ballot_sync(0xFFFFFFFFu, best >= 0.5f);
    unsigned nb = __ballot_sync(0xFFFFFFFFu, best < 0.4f);
    if ((tid & 31) == 0) { atomicAdd(&snp, __popc(pb)); atomicAdd(&snn, __popc(nb)); }

    // fused 1/32-sampled focal histogram (all anchors; contamination absorbed by slack)
    if (tid < THR / 32) {
        int sa = blockIdx.x * THR + tid * 32;
        const float* cp = conf + ((size_t)b * AA + sa) * CC;
        float p[CC];
#pragma unroll
        for (int c = 0; c < CC; c++) p[c] = cp[c];
        softmax21(p);
#pragma unroll
        for (int c = 0; c < CC; c++) {
            float f = focal_fn(p[c], false);
            atomicAdd(&sh[focal_bin(f)], 1u);
        }
    }
    __syncthreads();
    if (tid < TT) { unsigned long long v = smax[tid]; if (v) atomicMax(&g.packed[b][tid], v); }
    if (tid == 0) { atomicAdd(&g.numpos[b], snp); atomicAdd(&g.nneg[b], snn); }
    for (int i = tid; i < NB1; i += THR)
        if (sh[i]) atomicAdd(&g.h0[b][i], sh[i]);
}

// -------------- k2: per-image: apply force-match, fix counts, pick blo/k
__global__ void kPrep() {
    int b = blockIdx.x, tid = threadIdx.x;
    __shared__ unsigned int hc[NB1];
    __shared__ unsigned int scnt[256];
    __shared__ int s_found, s_bin;
    __shared__ long long s_cum;
    __shared__ float s_sum;
    if (tid < TT) {
        unsigned a = 0xFFFFFFFFu - (unsigned)(g.packed[b][tid] & 0xFFFFFFFFull);
        if (a < AA) {
            unsigned bit = 1u << (a & 31);
            unsigned old = atomicOr(&g.forced[b][a >> 5], bit);
            if (!(old & bit)) {
                float mi = g_maxiou[b * AA + a];
                if (mi < 0.5f) atomicAdd(&g.numpos[b], 1);
                if (mi < 0.4f) atomicAdd(&g.nneg[b], -1);
            }
        }
    }
    for (int i = tid; i < NB1; i += THR) hc[i] = g.h0[b][i];
    __syncthreads();
    long long np = g.numpos[b], nn = g.nneg[b];
    long long k = 3 * np; if (nn < k) k = nn;
    if (tid == 0) g.kval[b] = (int)k;
    if (k <= 0) { if (tid == 0) g.blo[b] = NB1; return; }
    long long target = k / 16 + 128;       // expected survivors ~ 2k + 4096
    suffix_select<NB1, false>(hc, nullptr, target, scnt, nullptr,
                              &s_found, &s_bin, &s_cum, &s_sum);
    if (tid == 0) g.blo[b] = s_found ? s_bin : 0;
}

// ------------------- k3: main pass: focal, pos_sum, bbox loss, compaction
__global__ void kMain(const float* __restrict__ conf, const float* __restrict__ bbox,
                      const float* __restrict__ tb, const int* __restrict__ tl) {
    int b = blockIdx.y;
    int tid = threadIdx.x;
    int lane = tid & 31;
    int a0 = blockIdx.x * THR, a = a0 + tid;
    __shared__ float sc[THR * CC];
    __shared__ float stb[TT * 4];
    __shared__ int stl[TT];
    if (tid < TT * 4) stb[tid] = tb[b * TT * 4 + tid];
    if (tid < TT) stl[tid] = tl[b * TT + tid];
    size_t cb = ((size_t)b * AA + a0) * CC;
    for (int i = tid; i < THR * CC; i += THR) sc[i] = conf[cb + i];
    __syncthreads();

    float mi = g_maxiou[b * AA + a];
    bool forced = (g.forced[b][a >> 5] >> (a & 31)) & 1;
    bool pos = (mi >= 0.5f) || forced;
    bool neg = (mi < 0.4f) && !forced;
    int bt = g_bestt[b * AA + a];
    int tc = stl[bt];
    int blo = g.blo[b];

    float p[CC];
#pragma unroll
    for (int c = 0; c < CC; c++) p[c] = sc[tid * CC + c];  // stride 21: conflict-free
    softmax21(p);

    float ps = 0.f;
#pragma unroll
    for (int c = 0; c < CC; c++) {
        bool isp = pos && (c == tc);
        float f = focal_fn(p[c], isp);
        if (pos) ps += f;
        bool want = neg && (focal_bin(f) >= blo);
        unsigned m = __ballot_sync(0xFFFFFFFFu, want);
        if (m) {                                     // warp-aggregated compaction
            int leader = __ffs(m) - 1;
            int rank = __popc(m & ((1u << lane) - 1));
            int base = 0;
            if (lane == leader) base = atomicAdd(&g.cnt[b], __popc(m));
            base = __shfl_sync(0xFFFFFFFFu, base, leader);
            int idx = base + rank;
            if (want && idx < CAP) g_buf[b][idx] = f;
        }
    }

    float bb = 0.f;
    if (pos) {
        float4 bp = ((const float4*)bbox)[(size_t)b * AA + a];
        float t0 = stb[bt * 4], t1 = stb[bt * 4 + 1];
        float t2 = stb[bt * 4 + 2], t3 = stb[bt * 4 + 3];
        float x1 = fmaxf(bp.x, t0), y1 = fmaxf(bp.y, t1);
        float x2 = fminf(bp.z, t2), y2 = fminf(bp.w, t3);
        float inter = fmaxf(x2 - x1, 0.f) * fmaxf(y2 - y1, 0.f);
        float a1 = (bp.z - bp.x) * (bp.w - bp.y);
        float a2 = (t2 - t0) * (t3 - t1);
        float uni = a1 + a2 - inter;
        float iou = inter / (uni + 1e-6f);
        float ex1 = fminf(bp.x, t0), ey1 = fminf(bp.y, t1);
        float ex2 = fmaxf(bp.z, t2), ey2 = fmaxf(bp.w, t3);
        float enc = (ex2 - ex1) * (ey2 - ey1);
        float gl = 1.f - (iou - (enc - uni) / (enc + 1e-6f));
        float l1 = 0.f, d, ad;
        d = bp.x - t0; ad = fabsf(d); l1 += (ad < 1.f) ? 0.5f * d * d : ad - 0.5f;
        d = bp.y - t1; ad = fabsf(d); l1 += (ad < 1.f) ? 0.5f * d * d : ad - 0.5f;
        d = bp.z - t2; ad = fabsf(d); l1 += (ad < 1.f) ? 0.5f * d * d : ad - 0.5f;
        d = bp.w - t3; ad = fabsf(d); l1 += (ad < 1.f) ? 0.5f * d * d : ad - 0.5f;
        l1 *= 0.25f;
        bb = gl + 0.5f * l1;
    } else {
        ps = 0.f;
    }
    // warp-reduce pos contributions -> 1 atomic/warp
#pragma unroll
    for (int off = 16; off > 0; off >>= 1) {
        ps += __shfl_down_sync(0xFFFFFFFFu, ps, off);
        bb += __shfl_down_sync(0xFFFFFFFFu, bb, off);
    }
    if (lane == 0) {
        if (ps != 0.f) atomicAdd(&g.possum[b], ps);
        if (bb != 0.f) atomicAdd(&g.bboxsum[b], bb);
    }
}

// ----------------- k4: exact top-k on compacted values (2-level radix)
// NOTE: must be launched with exactly 256 threads (suffix_select contract)
__global__ void kSelect() {
    int b = blockIdx.x, tid = threadIdx.x;
    __shared__ unsigned int hc[NB2];
    __shared__ float hs[NB2];
    __shared__ unsigned int scnt[256];
    __shared__ float ssum[256];
    __shared__ int s_found, s_bin;
    __shared__ long long s_cum;
    __shared__ float s_sum;
    int n = g.cnt[b];
    long long k = g.kval[b];
    long long np = g.numpos[b];
    bool bad = (n > CAP);
    float topk = 0.f;
    if (k > 0 && !bad) {
        for (int i = tid; i < NB1; i += THR) { hc[i] = 0; hs[i] = 0.f; }
        __syncthreads();
        for (int i = tid; i < n; i += THR) {
            float v = g_buf[b][i];
            int bin = focal_bin(v);
            atomicAdd(&hc[bin], 1u);
            atomicAdd(&hs[bin], v);
        }
        __syncthreads();
        suffix_select<NB1, true>(hc, hs, k, scnt, ssum, &s_found, &s_bin, &s_cum, &s_sum);
        if (!s_found) {
            bad = true;                                 // under-coverage -> fallback
        } else {
            int bstar = s_bin;
            long long rem = k - s_cum;
            float above = s_sum;
            unsigned cstar = hc[bstar];
            float sstar = hs[bstar];
            __syncthreads();
            if (rem >= (long long)cstar) {
                topk = above + sstar;                   // consume whole bin exactly
            } else {
                // level-2 refinement inside bstar
                for (int i = tid; i < NB2; i += THR) { hc[i] = 0; hs[i] = 0.f; }
                __syncthreads();
                for (int i = tid; i < n; i += THR) {
                    float v = g_buf[b][i];
                    unsigned bits = __float_as_uint(v) & 0x7FFFFFFFu;
                    if ((int)(bits >> 20) == bstar) {
                        int sb = (bits >> 8) & 0xFFF;
                        atomicAdd(&hc[sb], 1u);
                        atomicAdd(&hs[sb], v);
                    }
                }
                __syncthreads();
                suffix_select<NB2, true>(hc, hs, rem, scnt, ssum, &s_found, &s_bin, &s_cum, &s_sum);
                long long rem2 = rem - s_cum;
                float part = 0.f;
                unsigned c2 = hc[s_bin];
                if (rem2 >= (long long)c2) part = hs[s_bin];
                else if (rem2 > 0 && c2 > 0) part = (float)rem2 * (hs[s_bin] / (float)c2);
                topk = above + s_sum + part;
            }
        }
    }
    if (tid == 0) {
        if (bad && k > 0) {
            g.redo[b] = 1;
        } else {
            long long dn = np + k; if (dn < 1) dn = 1;
            g.confl[b] = (g.possum[b] + topk) / (float)dn;
        }
        g.bboxl[b] = (np > 0) ? g.bboxsum[b] / (float)np : 0.f;
    }
}

// --------- k5/k6: fallback (full histogram) — uniform early-out when idle
__global__ void kFbHist(const float* __restrict__ conf) {
    int b = blockIdx.y;
    if (g.redo[b] == 0) return;
    int tid = threadIdx.x;
    int a0 = blockIdx.x * THR, a = a0 + tid;
    __shared__ float sc[THR * CC];
    __shared__ unsigned int hc[NB1];
    __shared__ float hs[NB1];
    for (int i = tid; i < NB1; i += THR) { hc[i] = 0; hs[i] = 0.f; }
    size_t cb = ((size_t)b * AA + a0) * CC;
    for (int i = tid; i < THR * CC; i += THR) sc[i] = conf[cb + i];
    __syncthreads();
    float mi = g_maxiou[b * AA + a];
    bool forced = (g.forced[b][a >> 5] >> (a & 31)) & 1;
    if (mi < 0.4f && !forced) {
        float p[CC];
#pragma unroll
        for (int c = 0; c < CC; c++) p[c] = sc[tid * CC + c];
        softmax21(p);
#pragma unroll
        for (int c = 0; c < CC; c++) {
            float f = focal_fn(p[c], false);
            int bin = focal_bin(f);
            atomicAdd(&hc[bin], 1u);
            atomicAdd(&hs[bin], f);
        }
    }
    __syncthreads();
    for (int i = tid; i < NB1; i += THR)
        if (hc[i]) { atomicAdd(&g.fcnt[b][i], hc[i]); atomicAdd(&g.fsum[b][i], hs[i]); }
}

__global__ void kFbSel() {
    int b = blockIdx.x;
    if (g.redo[b] == 0) return;
    int tid = threadIdx.x;
    __shared__ unsigned int hc[NB1];
    __shared__ float hs[NB1];
    __shared__ unsigned int scnt[256];
    __shared__ float ssum[256];
    __shared__ int s_found, s_bin;
    __shared__ long long s_cum;
    __shared__ float s_sum;
    for (int i = tid; i < NB1; i += THR) { hc[i] = g.fcnt[b][i]; hs[i] = g.fsum[b][i]; }
    __syncthreads();
    long long k = g.kval[b], np = g.numpos[b];
    suffix_select<NB1, true>(hc, hs, k, scnt, ssum, &s_found, &s_bin, &s_cum, &s_sum);
    if (tid) return;
    float ab = s_sum;
    long long rem = k - s_cum;
    unsigned c = hc[s_bin];
    if (rem >= (long long)c) ab += hs[s_bin];
    else if (rem > 0 && c > 0) ab += (float)rem * (hs[s_bin] / (float)c);
    long long dn = np + k; if (dn < 1) dn = 1;
    g.confl[b] = (g.possum[b] + ab) / (float)dn;
}

// --------------------------------------------------------- k7: finalize
__global__ void kFinal(float* out) {
    if (threadIdx.x == 0) {
        float cs = 0.f, bs = 0.f;
        for (int b = 0; b < BB; b++) { cs += g.confl[b]; bs += g.bboxl[b]; }
        cs *= (1.0f / BB); bs *= (1.0f / BB);
        out[0] = cs + bs;
        out[1] = cs;
        out[2] = bs;
    }
}

// ---------------------------------------------------------------- launch
extern "C" void kernel_launch(void* const* d_in, const int* in_sizes, int n_in,
                              void* d_out, int out_size) {
    const float* conf = (const float*)d_in[0];
    const float* bbox = (const float*)d_in[1];
    const float* anch = (const float*)d_in[2];
    const float* tb = (const float*)d_in[3];
    const int* tl = (const int*)d_in[4];
    float* out = (float*)d_out;

    int nz = (int)(sizeof(State) / 4);
    kZero<<<(nz + 255) / 256, 256>>>();
    kIoUSamp<<<dim3(AA / THR, BB), THR>>>(anch, tb, conf);
    kPrep<<<BB, THR>>>();
    kMain<<<dim3(AA / THR, BB), THR>>>(conf, bbox, tb, tl);
    kSelect<<<BB, THR>>>();            // 256 threads: suffix_select contract
    kFbHist<<<dim3(AA / THR, BB), THR>>>(conf);
    kFbSel<<<BB, THR>>>();
    kFinal<<<1, 32>>>(out);
}